// round 14
// baseline (speedup 1.0000x reference)
#include <cuda_runtime.h>
#include <cuda_fp16.h>
#include <cstdint>

#define B_ 128
#define T_ 256
#define F_ 128
#define NCAT_ 32
#define CARD_ 16
#define E_ 8
#define H_ 512
#define INPUT_LEN_ 352
#define NCONT_ 96
#define BT_ (B_*T_)
#define G4H_ 2048
#define NBLK_ 128          // LSTM persistent grid
#define LSTM_THREADS 512
#define WSTRIDE 520        // padded k-stride (halves) for conflict-free weight LDS
#define IMG_HALVES (32*WSTRIDE)          // one image: 32 n-rows (8 units x 4 gates) x 520
#define CTA_IMG_HALVES (4*IMG_HALVES)    // L0hi,L0lo,L1hi,L1lo = 133120 B

typedef unsigned long long ull;

// ---------------- scratch (device globals) ----------------
__device__ __align__(128) __half g_xin16h[(size_t)BT_*INPUT_LEN_];
__device__ __align__(128) __half g_Win16h[(size_t)H_*INPUT_LEN_];
__device__ __align__(128) __half g_Win16l[(size_t)H_*INPUT_LEN_];
__device__ __align__(128) __half g_x16h[(size_t)BT_*H_];
__device__ __align__(128) float  g_X0 [(size_t)BT_*G4H_];
__device__ __align__(128) __half g_W16h[(size_t)G4H_*H_];
__device__ __align__(128) __half g_W16l[(size_t)G4H_*H_];
__device__ float  g_b0[G4H_];
__device__ float  g_b1[G4H_];
__device__ __align__(128) __half g_img[(size_t)64*CTA_IMG_HALVES];   // 64 unit-group images
__device__ __align__(128) __half g_h16A[B_*H_];   // h0 (layer0 output)
__device__ __align__(128) __half g_h16B[B_*H_];   // h  (layer1 output)
__device__ float  g_h [B_*H_];
__device__ float  g_c [B_*H_];
__device__ __align__(128) unsigned g_pcnt[64];    // [0]: batch-half 0, [32]: batch-half 1

// ---------------- helpers ----------------
__device__ __forceinline__ float sigf(float x) { return 1.0f / (1.0f + __expf(-x)); }
__device__ __forceinline__ float tanhfast(float x) { return 2.0f*sigf(2.0f*x) - 1.0f; }
__device__ __forceinline__ uint32_t smem_u32(const void* p) {
    uint32_t a;
    asm("{ .reg .u64 t; cvta.to.shared.u64 t, %1; cvt.u32.u64 %0, t; }" : "=r"(a) : "l"(p));
    return a;
}
__device__ __forceinline__ unsigned ldacq(const unsigned* p) {
    unsigned v;
    asm volatile("ld.global.acquire.gpu.u32 %0, [%1];" : "=r"(v) : "l"(p));
    return v;
}
__device__ __forceinline__ void mma_f32(float* d, const uint32_t* a, const uint32_t* b) {
    asm volatile("mma.sync.aligned.m16n8k16.row.col.f32.f16.f16.f32 "
        "{%0,%1,%2,%3}, {%4,%5,%6,%7}, {%8,%9}, {%0,%1,%2,%3};"
        : "+f"(d[0]), "+f"(d[1]), "+f"(d[2]), "+f"(d[3])
        : "r"(a[0]), "r"(a[1]), "r"(a[2]), "r"(a[3]), "r"(b[0]), "r"(b[1]));
}
__device__ __forceinline__ void mma_f16acc(uint32_t* d, const uint32_t* a, const uint32_t* b) {
    asm volatile("mma.sync.aligned.m16n8k16.row.col.f16.f16.f16.f16 "
        "{%0,%1}, {%2,%3,%4,%5}, {%6,%7}, {%0,%1};"
        : "+r"(d[0]), "+r"(d[1])
        : "r"(a[0]), "r"(a[1]), "r"(a[2]), "r"(a[3]), "r"(b[0]), "r"(b[1]));
}
#define CP_ASYNC16(dst_u32, src_ptr) \
    asm volatile("cp.async.cg.shared.global [%0], [%1], 16;" :: "r"(dst_u32), "l"(src_ptr) : "memory")
#define CP_COMMIT() asm volatile("cp.async.commit_group;" ::: "memory")
#define CP_WAIT(n)  asm volatile("cp.async.wait_group %0;" :: "n"(n) : "memory")
#define LDSM_X4(r0,r1,r2,r3, a) \
    asm volatile("ldmatrix.sync.aligned.m8n8.x4.shared.b16 {%0,%1,%2,%3}, [%4];" \
        : "=r"(r0), "=r"(r1), "=r"(r2), "=r"(r3) : "r"(a))
#define NAMED_BAR128(id) asm volatile("bar.sync %0, 128;" :: "r"(id) : "memory")

// half-grid barrier: 64 CTAs of one batch-half, monotonic counter, per-warp wake
__device__ __forceinline__ void hsync(int half, unsigned p) {
    __syncthreads();
    if (threadIdx.x == 0) {
        __threadfence();
        atomicAdd(&g_pcnt[half*32], 1u);
    }
    const unsigned target = 64u * p;
    if ((threadIdx.x & 31) == 0) {
        if (ldacq(&g_pcnt[half*32]) < target) {
            do { __nanosleep(20); } while (ldacq(&g_pcnt[half*32]) < target);
        }
    }
    __syncwarp();
}

// ---------------- prep ----------------
// image row for gate-row n = g*512+u: uct=u>>3; uu=u&7; ng=uu>>1; du=uu&1;
// n_local = ng*8 + du*4 + g   (thread-pair friendly: D cols 2q,2q+1 = (du=q>>1, gates by q&1)
__global__ void prep_kernel(const float* __restrict__ Wih0, const float* __restrict__ Whh0,
                            const float* __restrict__ Wih1, const float* __restrict__ Whh1,
                            const float* __restrict__ bih0, const float* __restrict__ bhh0,
                            const float* __restrict__ bih1, const float* __restrict__ bhh1) {
    int n = blockIdx.x;      // 0..2047
    int k = threadIdx.x;     // 0..511
    if (blockIdx.x == 0 && threadIdx.x < 64) g_pcnt[threadIdx.x] = 0u;

    float wih0 = Wih0[n*H_ + k];
    float whh0 = Whh0[n*H_ + k];
    float w1   = Wih1[n*H_ + k] + Whh1[n*H_ + k];

    __half wh = __float2half_rn(wih0);
    g_W16h[(size_t)n*H_ + k] = wh;
    g_W16l[(size_t)n*H_ + k] = __float2half_rn((wih0 - __half2float(wh))*2048.0f);

    int g = n >> 9, u = n & 511;
    int uct = u >> 3;
    int uu = u & 7;
    int ng = uu >> 1;
    int du = uu & 1;
    int n_local = ng*8 + du*4 + g;
    size_t base = (size_t)uct * CTA_IMG_HALVES + (size_t)n_local * WSTRIDE + k;
    __half h0hi = __float2half(whh0);
    __half h0lo = __float2half((whh0 - __half2float(h0hi)) * 2048.0f);
    __half h1hi = __float2half(w1);
    __half h1lo = __float2half((w1 - __half2float(h1hi)) * 2048.0f);
    g_img[base + 0*IMG_HALVES] = h0hi;
    g_img[base + 1*IMG_HALVES] = h0lo;
    g_img[base + 2*IMG_HALVES] = h1hi;
    g_img[base + 3*IMG_HALVES] = h1lo;

    if (k == 0) {
        g_b0[n] = bih0[n] + bhh0[n];
        g_b1[n] = bih1[n] + bhh1[n];
    }
}

__global__ void prep_win_kernel(const float* __restrict__ W_in) {
    int k = blockIdx.x;      // 0..351
    int n = threadIdx.x;     // 0..511
    float v = W_in[(size_t)k*H_ + n];
    __half hi = __float2half_rn(v);
    g_Win16h[(size_t)n*INPUT_LEN_ + k] = hi;
    g_Win16l[(size_t)n*INPUT_LEN_ + k] = __float2half_rn((v - __half2float(hi))*2048.0f);
}

// ---------------- build xin (fp16 hi only) ----------------
__global__ void build_xin_kernel(const int* __restrict__ unscaled,
                                 const float* __restrict__ scaled,
                                 const float* __restrict__ emb) {
    int bt = blockIdx.x;
    int i  = threadIdx.x;
    int k  = i / 11;
    int j  = i - k*11;
    float v;
    if (j < 8) {
        int cid = unscaled[(size_t)bt*F_ + 4*k];
        v = emb[(k*CARD_ + cid)*E_ + j];
    } else {
        v = scaled[(size_t)bt*F_ + 4*k + (j - 8) + 1];
    }
    g_xin16h[(size_t)bt*INPUT_LEN_ + i] = __float2half_rn(v);
}

// ---------------- HMMA GEMM tiles ----------------
#define GT_BUF_B 30720
#define GT_A_OFF 0
#define GT_WH_OFF 10240
#define GT_WL_OFF 20480

__device__ __forceinline__ void gt_stage(uint32_t sbase, int buf, int m0, int n0, int kb, int tid,
                                         const __half* __restrict__ A, int strideA,
                                         const __half* __restrict__ Wh,
                                         const __half* __restrict__ Wl, int strideW) {
    uint32_t b = sbase + buf*GT_BUF_B;
    #pragma unroll
    for (int rep = 0; rep < 2; rep++) {
        int i = rep*256 + tid;
        int row = i >> 2, c = i & 3;
        uint32_t doff = (uint32_t)(row*40 + c*8)*2;
        CP_ASYNC16(b + GT_A_OFF  + doff, A  + (size_t)(m0+row)*strideA + kb + c*8);
        CP_ASYNC16(b + GT_WH_OFF + doff, Wh + (size_t)(n0+row)*strideW + kb + c*8);
        CP_ASYNC16(b + GT_WL_OFF + doff, Wl + (size_t)(n0+row)*strideW + kb + c*8);
    }
}

template<int KITERS>
__device__ __forceinline__ void gt_mainloop(uint32_t sbase, const __half* g2s,
                                            int m0, int n0, int tid,
                                            const __half* __restrict__ A, int strideA,
                                            const __half* __restrict__ Wh,
                                            const __half* __restrict__ Wl, int strideW,
                                            float accM[2][8][4], uint32_t accC[2][8][2]) {
    const int lane = tid & 31, wid = tid >> 5;
    const int wm = wid & 3, wn = wid >> 2;
    const int r = lane >> 2, q = lane & 3;

    gt_stage(sbase, 0, m0, n0, 0, tid, A, strideA, Wh, Wl, strideW); CP_COMMIT();

    #pragma unroll 1
    for (int it = 0; it < KITERS; it++) {
        if (it < KITERS-1) {
            gt_stage(sbase, (it+1)&1, m0, n0, (it+1)*32, tid, A, strideA, Wh, Wl, strideW);
            CP_COMMIT();
            CP_WAIT(1);
        } else {
            CP_WAIT(0);
        }
        __syncthreads();
        const __half* sA  = g2s + ((it&1)*GT_BUF_B + GT_A_OFF )/2;
        const __half* sWh = g2s + ((it&1)*GT_BUF_B + GT_WH_OFF)/2;
        const __half* sWl = g2s + ((it&1)*GT_BUF_B + GT_WL_OFF)/2;
        #pragma unroll
        for (int kk = 0; kk < 32; kk += 16) {
            uint32_t a[2][4];
            #pragma unroll
            for (int mt = 0; mt < 2; mt++) {
                const __half* p = sA + (wm*32 + mt*16 + r)*40 + kk + q*2;
                a[mt][0] = *(const uint32_t*)p;
                a[mt][1] = *(const uint32_t*)(p + 8*40);
                a[mt][2] = *(const uint32_t*)(p + 8);
                a[mt][3] = *(const uint32_t*)(p + 8*40 + 8);
            }
            #pragma unroll
            for (int nt = 0; nt < 8; nt++) {
                const __half* ph = sWh + (wn*64 + nt*8 + r)*40 + kk + q*2;
                const __half* pl = sWl + (wn*64 + nt*8 + r)*40 + kk + q*2;
                uint32_t bh[2] = {*(const uint32_t*)ph, *(const uint32_t*)(ph+8)};
                uint32_t bl[2] = {*(const uint32_t*)pl, *(const uint32_t*)(pl+8)};
                #pragma unroll
                for (int mt = 0; mt < 2; mt++) {
                    mma_f32(accM[mt][nt], a[mt], bh);
                    mma_f16acc(accC[mt][nt], a[mt], bl);
                }
            }
        }
        __syncthreads();
    }
}

// gemm1: x = relu(xin@W_in + b_in), fp16 output
__global__ void __launch_bounds__(256, 2) gemm1_kernel(const float* __restrict__ b_in) {
    extern __shared__ __half g2s[];
    const int tid = threadIdx.x, lane = tid & 31, wid = tid >> 5;
    const int wm = wid & 3, wn = wid >> 2;
    const int r = lane >> 2, q = lane & 3;
    const int m0 = blockIdx.x * 128;
    const int n0 = blockIdx.y * 128;
    uint32_t sbase = smem_u32(g2s);

    float accM[2][8][4]; uint32_t accC[2][8][2];
    #pragma unroll
    for (int mt = 0; mt < 2; mt++)
        #pragma unroll
        for (int nt = 0; nt < 8; nt++) {
            #pragma unroll
            for (int i = 0; i < 4; i++) accM[mt][nt][i] = 0.0f;
            accC[mt][nt][0] = 0u; accC[mt][nt][1] = 0u;
        }

    gt_mainloop<11>(sbase, g2s, m0, n0, tid, g_xin16h, INPUT_LEN_, g_Win16h, g_Win16l, INPUT_LEN_, accM, accC);

    const float s = 1.0f/2048.0f;
    #pragma unroll
    for (int mt = 0; mt < 2; mt++) {
        int gr0 = m0 + wm*32 + mt*16 + r;
        #pragma unroll
        for (int nt = 0; nt < 8; nt++) {
            int col = n0 + wn*64 + nt*8 + q*2;
            float bv0 = b_in[col], bv1 = b_in[col+1];
            __half2 lo01 = *reinterpret_cast<__half2*>(&accC[mt][nt][0]);
            __half2 lo23 = *reinterpret_cast<__half2*>(&accC[mt][nt][1]);
            float v00 = fmaxf(accM[mt][nt][0] + __half2float(__low2half(lo01))*s + bv0, 0.f);
            float v01 = fmaxf(accM[mt][nt][1] + __half2float(__high2half(lo01))*s + bv1, 0.f);
            float v10 = fmaxf(accM[mt][nt][2] + __half2float(__low2half(lo23))*s + bv0, 0.f);
            float v11 = fmaxf(accM[mt][nt][3] + __half2float(__high2half(lo23))*s + bv1, 0.f);
            size_t o0 = (size_t)gr0*H_ + col, o1 = (size_t)(gr0+8)*H_ + col;
            *(__half2*)(g_x16h + o0) = __halves2half2(__float2half_rn(v00), __float2half_rn(v01));
            *(__half2*)(g_x16h + o1) = __halves2half2(__float2half_rn(v10), __float2half_rn(v11));
        }
    }
}

// gemm2: X0 = x@Wih0^T + b0 (fp32 out, [bt][gate*H+unit])
__global__ void __launch_bounds__(256, 2) gemm2_kernel() {
    extern __shared__ __half g2s[];
    const int tid = threadIdx.x, lane = tid & 31, wid = tid >> 5;
    const int wm = wid & 3, wn = wid >> 2;
    const int r = lane >> 2, q = lane & 3;
    const int m0 = blockIdx.x * 128;
    const int n0 = blockIdx.y * 128;
    uint32_t sbase = smem_u32(g2s);

    float accM[2][8][4]; uint32_t accC[2][8][2];
    #pragma unroll
    for (int mt = 0; mt < 2; mt++)
        #pragma unroll
        for (int nt = 0; nt < 8; nt++) {
            #pragma unroll
            for (int i = 0; i < 4; i++) accM[mt][nt][i] = 0.0f;
            accC[mt][nt][0] = 0u; accC[mt][nt][1] = 0u;
        }

    gt_mainloop<16>(sbase, g2s, m0, n0, tid, g_x16h, H_, g_W16h, g_W16l, H_, accM, accC);

    const float s = 1.0f/2048.0f;
    #pragma unroll
    for (int mt = 0; mt < 2; mt++) {
        int gr0 = m0 + wm*32 + mt*16 + r;
        #pragma unroll
        for (int nt = 0; nt < 8; nt++) {
            int col = n0 + wn*64 + nt*8 + q*2;
            float b0a = g_b0[col], b0b = g_b0[col+1];
            __half2 lo01 = *reinterpret_cast<__half2*>(&accC[mt][nt][0]);
            __half2 lo23 = *reinterpret_cast<__half2*>(&accC[mt][nt][1]);
            float2 o0, o1;
            o0.x = accM[mt][nt][0] + __half2float(__low2half(lo01))*s + b0a;
            o0.y = accM[mt][nt][1] + __half2float(__high2half(lo01))*s + b0b;
            o1.x = accM[mt][nt][2] + __half2float(__low2half(lo23))*s + b0a;
            o1.y = accM[mt][nt][3] + __half2float(__high2half(lo23))*s + b0b;
            *(float2*)(g_X0 + (size_t)gr0*G4H_ + col) = o0;
            *(float2*)(g_X0 + (size_t)(gr0+8)*G4H_ + col) = o1;
        }
    }
}

// ---------------- HMMA persistent LSTM — 512 threads, 16 warps ----------------
// CTA ct: batches [(ct&1)*64, +64), units [(ct>>1)*8, +8).
// Warp w: bm = w>>2 (batches [bm*16,+16)), ng = w&3 (n-rows [ng*8,+8) = units ng*2, ng*2+1).
// 4 warps of a bm group share one 16-row A buffer; each stages 4 rows. Named bar = 128 threads.
// Thread: q=lane&3, r=lane>>2, e=q&1, du=q>>1 -> after shfl.bfly(1): handles
// (batch = gb0 + r + e*8, unit = uct*8 + ng*2 + du) with all 4 gates.
#define SH_OFF CTA_IMG_HALVES
#define LSTM_SMEM_B ((CTA_IMG_HALVES + 64*H_)*2)   // 133120 + 65536 = 198656

template<int LAYER>
__device__ __forceinline__ void lstm_phase(int t, int mb0, int uct, int tid,
                                           const __half* __restrict__ hsrc,
                                           __half* __restrict__ hdst,
                                           const __half* __restrict__ sW,
                                           uint32_t sA_base,
                                           float& creg,
                                           const float* __restrict__ bb,
                                           int batch, int unit) {
    const int w = tid >> 5, lane = tid & 31;
    const int bm = w >> 2, ng = w & 3;
    const int q = lane & 3, r = lane >> 2;
    const int e = q & 1;
    const int gb0 = mb0 + bm*16;
    const uint32_t pairbase = sA_base + (uint32_t)bm*16384;

    // stage this warp's 4 rows of the group's 16-row buffer, 4 chunks of 128 cols
    #pragma unroll
    for (int j = 0; j < 4; j++) {
        #pragma unroll
        for (int seg = 0; seg < 2; seg++) {
            int i = seg*32 + lane;
            int rl = i >> 4, c = i & 15;
            int row = ng*4 + rl;
            uint32_t dst = pairbase + (uint32_t)row*1024 + ((uint32_t)((j*16 + c) ^ (row & 7)) << 4);
            CP_ASYNC16(dst, hsrc + (size_t)(gb0 + row)*H_ + (j*16 + c)*8);
        }
        CP_COMMIT();
    }

    // X0 prefetch for this thread's (batch, unit)
    float x0r[4];
    if (LAYER == 0) {
        const float* xb = g_X0 + ((size_t)batch*T_ + t)*G4H_ + unit;
        #pragma unroll
        for (int g = 0; g < 4; g++) x0r[g] = __ldg(xb + g*H_);
    }

    float accH[4];
    uint32_t accLC[2];
    #pragma unroll
    for (int i = 0; i < 4; i++) accH[i] = 0.f;
    accLC[0] = 0u; accLC[1] = 0u;

    const uint32_t rowAddr = pairbase + (uint32_t)(lane & 15)*1024;
    const int sw = lane & 7;
    const int khalf = lane >> 4;
    const __half* wHi = sW + (LAYER*2 + 0)*IMG_HALVES + (ng*8 + r)*WSTRIDE + q*2;
    const __half* wLo = wHi + IMG_HALVES;

    auto mma_chunk = [&](int j) {
        #pragma unroll
        for (int kk = 0; kk < 8; kk++) {
            int k0 = j*128 + kk*16;
            uint32_t coff = ((uint32_t)((j*16 + kk*2 + khalf) ^ sw)) << 4;
            uint32_t a[4];
            LDSM_X4(a[0], a[1], a[2], a[3], rowAddr + coff);
            const __half* ph = wHi + k0;
            const __half* pl = wLo + k0;
            uint32_t bh[2] = {*(const uint32_t*)ph, *(const uint32_t*)(ph+8)};
            uint32_t bl[2] = {*(const uint32_t*)pl, *(const uint32_t*)(pl+8)};
            mma_f32(accH, a, bh);
            mma_f16acc(accLC, a, bl);
        }
    };

    CP_WAIT(3); NAMED_BAR128(1 + bm); mma_chunk(0);
    CP_WAIT(2); NAMED_BAR128(1 + bm); mma_chunk(1);
    CP_WAIT(1); NAMED_BAR128(1 + bm); mma_chunk(2);
    CP_WAIT(0); NAMED_BAR128(1 + bm); mma_chunk(3);

    // pair exchange: thread pair (q, q^1) holds the two gate-pairs of unit du for rows r / r+8
    float oh0 = __shfl_xor_sync(0xffffffffu, accH[0], 1);
    float oh1 = __shfl_xor_sync(0xffffffffu, accH[1], 1);
    float oh2 = __shfl_xor_sync(0xffffffffu, accH[2], 1);
    float oh3 = __shfl_xor_sync(0xffffffffu, accH[3], 1);
    uint32_t ol0 = __shfl_xor_sync(0xffffffffu, accLC[0], 1);
    uint32_t ol1 = __shfl_xor_sync(0xffffffffu, accLC[1], 1);

    float vi, vf, vg, vo;
    __half2 lif, lgo;
    if (e == 0) {     // even: own (i,f) row r; recv (g,o) row r
        vi = accH[0]; vf = accH[1]; vg = oh0; vo = oh1;
        lif = *reinterpret_cast<__half2*>(&accLC[0]);
        lgo = *reinterpret_cast<__half2*>(&ol0);
    } else {          // odd: own (g,o) row r+8; recv (i,f) row r+8
        vi = oh2; vf = oh3; vg = accH[2]; vo = accH[3];
        lif = *reinterpret_cast<__half2*>(&ol1);
        lgo = *reinterpret_cast<__half2*>(&accLC[1]);
    }
    const float s = 1.0f / 2048.0f;
    vi += __half2float(__low2half(lif))*s;
    vf += __half2float(__high2half(lif))*s;
    vg += __half2float(__low2half(lgo))*s;
    vo += __half2float(__high2half(lgo))*s;
    if (LAYER == 0) {
        vi += x0r[0]; vf += x0r[1]; vg += x0r[2]; vo += x0r[3];
    } else {
        vi += bb[0]; vf += bb[1]; vg += bb[2]; vo += bb[3];
    }
    float cn = sigf(vf)*creg + sigf(vi)*tanhfast(vg);
    creg = cn;
    float hv = sigf(vo)*tanhfast(cn);
    hdst[(size_t)batch*H_ + unit] = __float2half_rn(hv);
    if (LAYER == 1 && t == T_-1) {
        g_h[batch*H_ + unit] = hv;
        g_c[batch*H_ + unit] = cn;
    }
}

__global__ void __launch_bounds__(LSTM_THREADS, 1) lstm_kernel() {
    extern __shared__ __half smemL[];
    __half* sW = smemL;
    uint32_t sA_base = smem_u32(smemL + SH_OFF);
    const int tid = threadIdx.x, lane = tid & 31;
    const int w = tid >> 5;
    const int ct = blockIdx.x;
    const int half = ct & 1;
    const int mb0 = half * 64;
    const int uct = ct >> 1;

    // copy resident weight images (133120 B)
    {
        const uint4* src = (const uint4*)(g_img + (size_t)uct*CTA_IMG_HALVES);
        uint4* dst = (uint4*)sW;
        #pragma unroll 4
        for (int i = tid; i < CTA_IMG_HALVES/8; i += LSTM_THREADS)
            dst[i] = src[i];
    }
    const int bm = w >> 2, ng = w & 3;
    const int q = lane & 3, r = lane >> 2;
    const int unit = uct*8 + ng*2 + (q >> 1);
    const int batch = mb0 + bm*16 + r + (q & 1)*8;
    float bb[4];
    #pragma unroll
    for (int g = 0; g < 4; g++) bb[g] = g_b1[g*H_ + unit];

    // zero initial h16B slice: 64 batches x 8 units (16B per row)
    if (tid < 64)
        *(uint4*)(g_h16B + (size_t)(mb0 + tid)*H_ + uct*8) = make_uint4(0u,0u,0u,0u);

    float creg = 0.f;
    unsigned p = 1;
    hsync(half, p); p++;   // all half-grid h16 slices visible

    for (int t = 0; t < T_; t++) {
        lstm_phase<0>(t, mb0, uct, tid, g_h16B, g_h16A, sW, sA_base, creg, bb, batch, unit);
        hsync(half, p); p++;
        lstm_phase<1>(t, mb0, uct, tid, g_h16A, g_h16B, sW, sA_base, creg, bb, batch, unit);
        hsync(half, p); p++;
    }
}

// ---------------- output heads ----------------
__global__ void __launch_bounds__(512) output_kernel(const float* __restrict__ W_out,
                                                     const float* __restrict__ b_out,
                                                     const float* __restrict__ W_cls,
                                                     const float* __restrict__ b_cls,
                                                     float* __restrict__ out) {
    __shared__ float hb[H_];
    int b = blockIdx.x, tid = threadIdx.x;
    hb[tid] = g_h[b*H_ + tid];
    __syncthreads();

    int kk = tid >> 4, cc = tid & 15;
    float acc = 0.0f;
    #pragma unroll 8
    for (int k = 0; k < H_; k++)
        acc = fmaf(hb[k], W_cls[(size_t)kk*H_*CARD_ + k*CARD_ + cc], acc);
    out[12288 + b*512 + tid] = acc + b_cls[tid];

    if (tid < NCONT_) {
        float a2 = 0.0f;
        #pragma unroll 8
        for (int k = 0; k < H_; k++)
            a2 = fmaf(hb[k], W_out[k*NCONT_ + tid], a2);
        out[b*NCONT_ + tid] = a2 + b_out[tid];
    }
    out[77824  + b*512 + tid] = hb[tid];
    out[143360 + b*512 + tid] = g_c[b*H_ + tid];
}

// ---------------- entry ----------------
extern "C" void kernel_launch(void* const* d_in, const int* in_sizes, int n_in,
                              void* d_out, int out_size) {
    (void)in_sizes; (void)n_in; (void)out_size;
    const int*   unscaled = (const int*)  d_in[0];
    const float* scaled   = (const float*)d_in[1];
    const float* emb      = (const float*)d_in[2];
    const float* W_in     = (const float*)d_in[3];
    const float* b_in     = (const float*)d_in[4];
    const float* Wih0     = (const float*)d_in[5];
    const float* Whh0     = (const float*)d_in[6];
    const float* bih0     = (const float*)d_in[7];
    const float* bhh0     = (const float*)d_in[8];
    const float* Wih1     = (const float*)d_in[9];
    const float* Whh1     = (const float*)d_in[10];
    const float* bih1     = (const float*)d_in[11];
    const float* bhh1     = (const float*)d_in[12];
    const float* W_out    = (const float*)d_in[13];
    const float* b_out    = (const float*)d_in[14];
    const float* W_cls    = (const float*)d_in[15];
    const float* b_cls    = (const float*)d_in[16];
    float* out = (float*)d_out;

    cudaFuncSetAttribute(lstm_kernel,  cudaFuncAttributeMaxDynamicSharedMemorySize, LSTM_SMEM_B);
    cudaFuncSetAttribute(gemm1_kernel, cudaFuncAttributeMaxDynamicSharedMemorySize, 2*GT_BUF_B);
    cudaFuncSetAttribute(gemm2_kernel, cudaFuncAttributeMaxDynamicSharedMemorySize, 2*GT_BUF_B);

    prep_kernel<<<G4H_, H_>>>(Wih0, Whh0, Wih1, Whh1, bih0, bhh0, bih1, bhh1);
    prep_win_kernel<<<INPUT_LEN_, H_>>>(W_in);
    build_xin_kernel<<<BT_, INPUT_LEN_>>>(unscaled, scaled, emb);
    gemm1_kernel<<<dim3(BT_/128, H_/128), 256, 2*GT_BUF_B>>>(b_in);
    gemm2_kernel<<<dim3(BT_/128, G4H_/128), 256, 2*GT_BUF_B>>>();
    lstm_kernel<<<NBLK_, LSTM_THREADS, LSTM_SMEM_B>>>();
    output_kernel<<<B_, 512>>>(W_out, b_out, W_cls, b_cls, out);
}

// round 15
// speedup vs baseline: 1.1391x; 1.1391x over previous
#include <cuda_runtime.h>
#include <cuda_fp16.h>
#include <cstdint>

#define B_ 128
#define T_ 256
#define F_ 128
#define NCAT_ 32
#define CARD_ 16
#define E_ 8
#define H_ 512
#define INPUT_LEN_ 352
#define NCONT_ 96
#define BT_ (B_*T_)
#define G4H_ 2048
#define NBLK_ 128          // LSTM persistent grid
#define LSTM_THREADS 256
#define WSTRIDE 520        // padded k-stride (halves) for conflict-free weight LDS
#define IMG_HALVES (32*WSTRIDE)          // one image: 32 n-rows (8 units x 4 gates) x 520
#define CTA_IMG_HALVES (4*IMG_HALVES)    // L0hi,L0lo,L1hi,L1lo = 133120 B

typedef unsigned long long ull;

// ---------------- scratch (device globals) ----------------
__device__ __align__(128) __half g_xin16h[(size_t)BT_*INPUT_LEN_];
__device__ __align__(128) __half g_Win16h[(size_t)H_*INPUT_LEN_];
__device__ __align__(128) __half g_Win16l[(size_t)H_*INPUT_LEN_];
__device__ __align__(128) __half g_x16h[(size_t)BT_*H_];
__device__ __align__(128) float  g_X0 [(size_t)BT_*G4H_];
__device__ __align__(128) __half g_W16h[(size_t)G4H_*H_];
__device__ __align__(128) __half g_W16l[(size_t)G4H_*H_];
__device__ float  g_b0[G4H_];
__device__ float  g_b1[G4H_];
__device__ __align__(128) __half g_img[(size_t)64*CTA_IMG_HALVES];   // 64 unit-group images
__device__ __align__(128) __half g_h16A[B_*H_];   // h0 (layer0 output)
__device__ __align__(128) __half g_h16B[B_*H_];   // h  (layer1 output)
__device__ float  g_h [B_*H_];
__device__ float  g_c [B_*H_];
__device__ __align__(128) unsigned g_pcnt[64];    // [0]: batch-half 0, [32]: batch-half 1

// ---------------- helpers ----------------
__device__ __forceinline__ float sigf(float x) { return 1.0f / (1.0f + __expf(-x)); }
__device__ __forceinline__ float tanhfast(float x) { return 2.0f*sigf(2.0f*x) - 1.0f; }
__device__ __forceinline__ uint32_t smem_u32(const void* p) {
    uint32_t a;
    asm("{ .reg .u64 t; cvta.to.shared.u64 t, %1; cvt.u32.u64 %0, t; }" : "=r"(a) : "l"(p));
    return a;
}
__device__ __forceinline__ unsigned ldacq(const unsigned* p) {
    unsigned v;
    asm volatile("ld.global.acquire.gpu.u32 %0, [%1];" : "=r"(v) : "l"(p));
    return v;
}
__device__ __forceinline__ void mma_f32(float* d, const uint32_t* a, const uint32_t* b) {
    asm volatile("mma.sync.aligned.m16n8k16.row.col.f32.f16.f16.f32 "
        "{%0,%1,%2,%3}, {%4,%5,%6,%7}, {%8,%9}, {%0,%1,%2,%3};"
        : "+f"(d[0]), "+f"(d[1]), "+f"(d[2]), "+f"(d[3])
        : "r"(a[0]), "r"(a[1]), "r"(a[2]), "r"(a[3]), "r"(b[0]), "r"(b[1]));
}
__device__ __forceinline__ void mma_f16acc(uint32_t* d, const uint32_t* a, const uint32_t* b) {
    asm volatile("mma.sync.aligned.m16n8k16.row.col.f16.f16.f16.f16 "
        "{%0,%1}, {%2,%3,%4,%5}, {%6,%7}, {%0,%1};"
        : "+r"(d[0]), "+r"(d[1])
        : "r"(a[0]), "r"(a[1]), "r"(a[2]), "r"(a[3]), "r"(b[0]), "r"(b[1]));
}
#define CP_ASYNC16(dst_u32, src_ptr) \
    asm volatile("cp.async.cg.shared.global [%0], [%1], 16;" :: "r"(dst_u32), "l"(src_ptr) : "memory")
#define CP_COMMIT() asm volatile("cp.async.commit_group;" ::: "memory")
#define CP_WAIT(n)  asm volatile("cp.async.wait_group %0;" :: "n"(n) : "memory")
#define LDSM_X4(r0,r1,r2,r3, a) \
    asm volatile("ldmatrix.sync.aligned.m8n8.x4.shared.b16 {%0,%1,%2,%3}, [%4];" \
        : "=r"(r0), "=r"(r1), "=r"(r2), "=r"(r3) : "r"(a))
#define NAMED_BAR(id) asm volatile("bar.sync %0, 64;" :: "r"(id) : "memory")

// half-grid barrier: 64 CTAs of one batch-half, monotonic counter, per-warp wake
__device__ __forceinline__ void hsync(int half, unsigned p) {
    __syncthreads();
    if (threadIdx.x == 0) {
        __threadfence();
        atomicAdd(&g_pcnt[half*32], 1u);
    }
    const unsigned target = 64u * p;
    if ((threadIdx.x & 31) == 0) {
        if (ldacq(&g_pcnt[half*32]) < target) {
            do { __nanosleep(20); } while (ldacq(&g_pcnt[half*32]) < target);
        }
    }
    __syncwarp();
}

// ---------------- prep ----------------
// unit-group images: uct = u>>3 owns units [uct*8,+8). Row layout within 32-row image:
// nh = (u>>2)&1 selects 16-row half; q = u&3, gate g:
// n_local = nh*16 + (g<2 ? 2q+g : 2q+8+(g-2))
__global__ void prep_kernel(const float* __restrict__ Wih0, const float* __restrict__ Whh0,
                            const float* __restrict__ Wih1, const float* __restrict__ Whh1,
                            const float* __restrict__ bih0, const float* __restrict__ bhh0,
                            const float* __restrict__ bih1, const float* __restrict__ bhh1) {
    int n = blockIdx.x;      // 0..2047
    int k = threadIdx.x;     // 0..511
    if (blockIdx.x == 0 && threadIdx.x < 64) g_pcnt[threadIdx.x] = 0u;

    float wih0 = Wih0[n*H_ + k];
    float whh0 = Whh0[n*H_ + k];
    float w1   = Wih1[n*H_ + k] + Whh1[n*H_ + k];

    __half wh = __float2half_rn(wih0);
    g_W16h[(size_t)n*H_ + k] = wh;
    g_W16l[(size_t)n*H_ + k] = __float2half_rn((wih0 - __half2float(wh))*2048.0f);

    int g = n >> 9, u = n & 511;
    int uct = u >> 3;
    int nh = (u >> 2) & 1;
    int q = u & 3;
    int n_local = nh*16 + ((g < 2) ? (2*q + g) : (2*q + 8 + (g - 2)));
    size_t base = (size_t)uct * CTA_IMG_HALVES + (size_t)n_local * WSTRIDE + k;
    __half h0hi = __float2half(whh0);
    __half h0lo = __float2half((whh0 - __half2float(h0hi)) * 2048.0f);
    __half h1hi = __float2half(w1);
    __half h1lo = __float2half((w1 - __half2float(h1hi)) * 2048.0f);
    g_img[base + 0*IMG_HALVES] = h0hi;
    g_img[base + 1*IMG_HALVES] = h0lo;
    g_img[base + 2*IMG_HALVES] = h1hi;
    g_img[base + 3*IMG_HALVES] = h1lo;

    if (k == 0) {
        g_b0[n] = bih0[n] + bhh0[n];
        g_b1[n] = bih1[n] + bhh1[n];
    }
}

__global__ void prep_win_kernel(const float* __restrict__ W_in) {
    int k = blockIdx.x;      // 0..351
    int n = threadIdx.x;     // 0..511
    float v = W_in[(size_t)k*H_ + n];
    __half hi = __float2half_rn(v);
    g_Win16h[(size_t)n*INPUT_LEN_ + k] = hi;
    g_Win16l[(size_t)n*INPUT_LEN_ + k] = __float2half_rn((v - __half2float(hi))*2048.0f);
}

// ---------------- build xin (fp16 hi only) ----------------
__global__ void build_xin_kernel(const int* __restrict__ unscaled,
                                 const float* __restrict__ scaled,
                                 const float* __restrict__ emb) {
    int bt = blockIdx.x;
    int i  = threadIdx.x;
    int k  = i / 11;
    int j  = i - k*11;
    float v;
    if (j < 8) {
        int cid = unscaled[(size_t)bt*F_ + 4*k];
        v = emb[(k*CARD_ + cid)*E_ + j];
    } else {
        v = scaled[(size_t)bt*F_ + 4*k + (j - 8) + 1];
    }
    g_xin16h[(size_t)bt*INPUT_LEN_ + i] = __float2half_rn(v);
}

// ---------------- HMMA GEMM tiles ----------------
#define GT_BUF_B 30720
#define GT_A_OFF 0
#define GT_WH_OFF 10240
#define GT_WL_OFF 20480

__device__ __forceinline__ void gt_stage(uint32_t sbase, int buf, int m0, int n0, int kb, int tid,
                                         const __half* __restrict__ A, int strideA,
                                         const __half* __restrict__ Wh,
                                         const __half* __restrict__ Wl, int strideW) {
    uint32_t b = sbase + buf*GT_BUF_B;
    #pragma unroll
    for (int rep = 0; rep < 2; rep++) {
        int i = rep*256 + tid;
        int row = i >> 2, c = i & 3;
        uint32_t doff = (uint32_t)(row*40 + c*8)*2;
        CP_ASYNC16(b + GT_A_OFF  + doff, A  + (size_t)(m0+row)*strideA + kb + c*8);
        CP_ASYNC16(b + GT_WH_OFF + doff, Wh + (size_t)(n0+row)*strideW + kb + c*8);
        CP_ASYNC16(b + GT_WL_OFF + doff, Wl + (size_t)(n0+row)*strideW + kb + c*8);
    }
}

template<int KITERS>
__device__ __forceinline__ void gt_mainloop(uint32_t sbase, const __half* g2s,
                                            int m0, int n0, int tid,
                                            const __half* __restrict__ A, int strideA,
                                            const __half* __restrict__ Wh,
                                            const __half* __restrict__ Wl, int strideW,
                                            float accM[2][8][4], uint32_t accC[2][8][2]) {
    const int lane = tid & 31, wid = tid >> 5;
    const int wm = wid & 3, wn = wid >> 2;
    const int r = lane >> 2, q = lane & 3;

    gt_stage(sbase, 0, m0, n0, 0, tid, A, strideA, Wh, Wl, strideW); CP_COMMIT();

    #pragma unroll 1
    for (int it = 0; it < KITERS; it++) {
        if (it < KITERS-1) {
            gt_stage(sbase, (it+1)&1, m0, n0, (it+1)*32, tid, A, strideA, Wh, Wl, strideW);
            CP_COMMIT();
            CP_WAIT(1);
        } else {
            CP_WAIT(0);
        }
        __syncthreads();
        const __half* sA  = g2s + ((it&1)*GT_BUF_B + GT_A_OFF )/2;
        const __half* sWh = g2s + ((it&1)*GT_BUF_B + GT_WH_OFF)/2;
        const __half* sWl = g2s + ((it&1)*GT_BUF_B + GT_WL_OFF)/2;
        #pragma unroll
        for (int kk = 0; kk < 32; kk += 16) {
            uint32_t a[2][4];
            #pragma unroll
            for (int mt = 0; mt < 2; mt++) {
                const __half* p = sA + (wm*32 + mt*16 + r)*40 + kk + q*2;
                a[mt][0] = *(const uint32_t*)p;
                a[mt][1] = *(const uint32_t*)(p + 8*40);
                a[mt][2] = *(const uint32_t*)(p + 8);
                a[mt][3] = *(const uint32_t*)(p + 8*40 + 8);
            }
            #pragma unroll
            for (int nt = 0; nt < 8; nt++) {
                const __half* ph = sWh + (wn*64 + nt*8 + r)*40 + kk + q*2;
                const __half* pl = sWl + (wn*64 + nt*8 + r)*40 + kk + q*2;
                uint32_t bh[2] = {*(const uint32_t*)ph, *(const uint32_t*)(ph+8)};
                uint32_t bl[2] = {*(const uint32_t*)pl, *(const uint32_t*)(pl+8)};
                #pragma unroll
                for (int mt = 0; mt < 2; mt++) {
                    mma_f32(accM[mt][nt], a[mt], bh);
                    mma_f16acc(accC[mt][nt], a[mt], bl);
                }
            }
        }
        __syncthreads();
    }
}

// gemm1: x = relu(xin@W_in + b_in), fp16 output
__global__ void __launch_bounds__(256, 2) gemm1_kernel(const float* __restrict__ b_in) {
    extern __shared__ __half g2s[];
    const int tid = threadIdx.x, lane = tid & 31, wid = tid >> 5;
    const int wm = wid & 3, wn = wid >> 2;
    const int r = lane >> 2, q = lane & 3;
    const int m0 = blockIdx.x * 128;
    const int n0 = blockIdx.y * 128;
    uint32_t sbase = smem_u32(g2s);

    float accM[2][8][4]; uint32_t accC[2][8][2];
    #pragma unroll
    for (int mt = 0; mt < 2; mt++)
        #pragma unroll
        for (int nt = 0; nt < 8; nt++) {
            #pragma unroll
            for (int i = 0; i < 4; i++) accM[mt][nt][i] = 0.0f;
            accC[mt][nt][0] = 0u; accC[mt][nt][1] = 0u;
        }

    gt_mainloop<11>(sbase, g2s, m0, n0, tid, g_xin16h, INPUT_LEN_, g_Win16h, g_Win16l, INPUT_LEN_, accM, accC);

    const float s = 1.0f/2048.0f;
    #pragma unroll
    for (int mt = 0; mt < 2; mt++) {
        int gr0 = m0 + wm*32 + mt*16 + r;
        #pragma unroll
        for (int nt = 0; nt < 8; nt++) {
            int col = n0 + wn*64 + nt*8 + q*2;
            float bv0 = b_in[col], bv1 = b_in[col+1];
            __half2 lo01 = *reinterpret_cast<__half2*>(&accC[mt][nt][0]);
            __half2 lo23 = *reinterpret_cast<__half2*>(&accC[mt][nt][1]);
            float v00 = fmaxf(accM[mt][nt][0] + __half2float(__low2half(lo01))*s + bv0, 0.f);
            float v01 = fmaxf(accM[mt][nt][1] + __half2float(__high2half(lo01))*s + bv1, 0.f);
            float v10 = fmaxf(accM[mt][nt][2] + __half2float(__low2half(lo23))*s + bv0, 0.f);
            float v11 = fmaxf(accM[mt][nt][3] + __half2float(__high2half(lo23))*s + bv1, 0.f);
            size_t o0 = (size_t)gr0*H_ + col, o1 = (size_t)(gr0+8)*H_ + col;
            *(__half2*)(g_x16h + o0) = __halves2half2(__float2half_rn(v00), __float2half_rn(v01));
            *(__half2*)(g_x16h + o1) = __halves2half2(__float2half_rn(v10), __float2half_rn(v11));
        }
    }
}

// gemm2: X0 = x@Wih0^T + b0 (fp32 out, [bt][gate*H+unit])
__global__ void __launch_bounds__(256, 2) gemm2_kernel() {
    extern __shared__ __half g2s[];
    const int tid = threadIdx.x, lane = tid & 31, wid = tid >> 5;
    const int wm = wid & 3, wn = wid >> 2;
    const int r = lane >> 2, q = lane & 3;
    const int m0 = blockIdx.x * 128;
    const int n0 = blockIdx.y * 128;
    uint32_t sbase = smem_u32(g2s);

    float accM[2][8][4]; uint32_t accC[2][8][2];
    #pragma unroll
    for (int mt = 0; mt < 2; mt++)
        #pragma unroll
        for (int nt = 0; nt < 8; nt++) {
            #pragma unroll
            for (int i = 0; i < 4; i++) accM[mt][nt][i] = 0.0f;
            accC[mt][nt][0] = 0u; accC[mt][nt][1] = 0u;
        }

    gt_mainloop<16>(sbase, g2s, m0, n0, tid, g_x16h, H_, g_W16h, g_W16l, H_, accM, accC);

    const float s = 1.0f/2048.0f;
    #pragma unroll
    for (int mt = 0; mt < 2; mt++) {
        int gr0 = m0 + wm*32 + mt*16 + r;
        #pragma unroll
        for (int nt = 0; nt < 8; nt++) {
            int col = n0 + wn*64 + nt*8 + q*2;
            float b0a = g_b0[col], b0b = g_b0[col+1];
            __half2 lo01 = *reinterpret_cast<__half2*>(&accC[mt][nt][0]);
            __half2 lo23 = *reinterpret_cast<__half2*>(&accC[mt][nt][1]);
            float2 o0, o1;
            o0.x = accM[mt][nt][0] + __half2float(__low2half(lo01))*s + b0a;
            o0.y = accM[mt][nt][1] + __half2float(__high2half(lo01))*s + b0b;
            o1.x = accM[mt][nt][2] + __half2float(__low2half(lo23))*s + b0a;
            o1.y = accM[mt][nt][3] + __half2float(__high2half(lo23))*s + b0b;
            *(float2*)(g_X0 + (size_t)gr0*G4H_ + col) = o0;
            *(float2*)(g_X0 + (size_t)(gr0+8)*G4H_ + col) = o1;
        }
    }
}

// ---------------- HMMA persistent LSTM — 64 batches x 8 units per CTA, half-grid barriers ----
// CTA ct: batches [(ct&1)*64, +64), units [(ct>>1)*8, +8) (32 gate-rows).
// Warp w = bm*2 + nh: batches [bm*16,+16) of CTA range, unit-half nh (4 units, 16 rows).
// Phase: stage all (1 commit) -> X0 prefetch -> wait+bar once -> 4 MMA chunks -> epilogue.
#define SH_OFF CTA_IMG_HALVES
#define LSTM_SMEM_B ((CTA_IMG_HALVES + 64*H_)*2)   // 133120 + 65536 = 198656

template<int LAYER>
__device__ __forceinline__ void lstm_phase(int t, int mb0, int uct, int tid,
                                           const __half* __restrict__ hsrc,
                                           __half* __restrict__ hdst,
                                           const __half* __restrict__ sW,
                                           uint32_t sA_base,
                                           float* __restrict__ creg,
                                           const float* __restrict__ bb) {
    const int w = tid >> 5, lane = tid & 31;
    const int bm = w >> 1, nh = w & 1;
    const int q = lane & 3, r = lane >> 2;
    const int unit = uct*8 + nh*4 + q;
    const int gb0 = mb0 + bm*16;
    const uint32_t pairbase = sA_base + (uint32_t)bm*16384;

    // stage this warp's 8 rows (all 512 cols), single commit
    #pragma unroll
    for (int j = 0; j < 4; j++) {
        #pragma unroll
        for (int seg = 0; seg < 4; seg++) {
            int i = seg*32 + lane;
            int rl = i >> 4, c = i & 15;
            int row = nh*8 + rl;
            uint32_t dst = pairbase + (uint32_t)row*1024 + ((uint32_t)((j*16 + c) ^ (row & 7)) << 4);
            CP_ASYNC16(dst, hsrc + (size_t)(gb0 + row)*H_ + (j*16 + c)*8);
        }
    }
    CP_COMMIT();

    // X0 / bias prefetch — overlaps all staging + peers' MMA
    float x0r[2][4];
    if (LAYER == 0) {
        #pragma unroll
        for (int hr = 0; hr < 2; hr++) {
            int batch = gb0 + hr*8 + r;
            const float* xb = g_X0 + ((size_t)batch*T_ + t)*G4H_ + unit;
            #pragma unroll
            for (int g = 0; g < 4; g++) x0r[hr][g] = __ldg(xb + g*H_);
        }
    }

    float accH[2][4];
    uint32_t accLC[2][2];
    #pragma unroll
    for (int nt = 0; nt < 2; nt++) {
        #pragma unroll
        for (int i = 0; i < 4; i++) accH[nt][i] = 0.f;
        accLC[nt][0] = 0u; accLC[nt][1] = 0u;
    }

    const uint32_t rowAddr = pairbase + (uint32_t)(lane & 15)*1024;
    const int sw = lane & 7;
    const int khalf = lane >> 4;
    const __half* wHi = sW + (LAYER*2 + 0)*IMG_HALVES + (nh*16 + r)*WSTRIDE + q*2;
    const __half* wLo = wHi + IMG_HALVES;

    CP_WAIT(0);
    NAMED_BAR(1 + bm);

    #pragma unroll
    for (int j = 0; j < 4; j++) {
        #pragma unroll
        for (int kk = 0; kk < 8; kk++) {
            int k0 = j*128 + kk*16;
            uint32_t coff = ((uint32_t)((j*16 + kk*2 + khalf) ^ sw)) << 4;
            uint32_t a[4];
            LDSM_X4(a[0], a[1], a[2], a[3], rowAddr + coff);
            #pragma unroll
            for (int nt = 0; nt < 2; nt++) {
                const __half* ph = wHi + nt*8*WSTRIDE + k0;
                const __half* pl = wLo + nt*8*WSTRIDE + k0;
                uint32_t bh[2] = {*(const uint32_t*)ph, *(const uint32_t*)(ph+8)};
                uint32_t bl[2] = {*(const uint32_t*)pl, *(const uint32_t*)(pl+8)};
                mma_f32(accH[nt], a, bh);
                mma_f16acc(accLC[nt], a, bl);
            }
        }
    }

    const float s = 1.0f / 2048.0f;
    #pragma unroll
    for (int hr = 0; hr < 2; hr++) {
        int batch = gb0 + hr*8 + r;
        __half2 l0 = *reinterpret_cast<__half2*>(&accLC[0][hr]);   // gates i,f
        __half2 l1 = *reinterpret_cast<__half2*>(&accLC[1][hr]);   // gates g,o
        float vi = accH[0][hr*2+0] + __half2float(__low2half(l0))*s;
        float vf = accH[0][hr*2+1] + __half2float(__high2half(l0))*s;
        float vg = accH[1][hr*2+0] + __half2float(__low2half(l1))*s;
        float vo = accH[1][hr*2+1] + __half2float(__high2half(l1))*s;
        if (LAYER == 0) {
            vi += x0r[hr][0]; vf += x0r[hr][1]; vg += x0r[hr][2]; vo += x0r[hr][3];
        } else {
            vi += bb[0]; vf += bb[1]; vg += bb[2]; vo += bb[3];
        }
        float c = creg[hr];
        float cn = sigf(vf)*c + sigf(vi)*tanhfast(vg);
        creg[hr] = cn;
        float hv = sigf(vo)*tanhfast(cn);
        hdst[(size_t)batch*H_ + unit] = __float2half_rn(hv);
        if (LAYER == 1 && t == T_-1) {
            g_h[batch*H_ + unit] = hv;
            g_c[batch*H_ + unit] = cn;
        }
    }
}

__global__ void __launch_bounds__(LSTM_THREADS, 1) lstm_kernel() {
    extern __shared__ __half smemL[];
    __half* sW = smemL;
    uint32_t sA_base = smem_u32(smemL + SH_OFF);
    const int tid = threadIdx.x, lane = tid & 31;
    const int w = tid >> 5;
    const int ct = blockIdx.x;
    const int half = ct & 1;
    const int mb0 = half * 64;
    const int uct = ct >> 1;

    // copy resident weight images (133120 B; sibling CTAs share the same image -> L2 hits)
    {
        const uint4* src = (const uint4*)(g_img + (size_t)uct*CTA_IMG_HALVES);
        uint4* dst = (uint4*)sW;
        #pragma unroll 4
        for (int i = tid; i < CTA_IMG_HALVES/8; i += LSTM_THREADS)
            dst[i] = src[i];
    }
    const int unit = uct*8 + (w & 1)*4 + (lane & 3);
    float bb[4];
    #pragma unroll
    for (int g = 0; g < 4; g++) bb[g] = g_b1[g*H_ + unit];

    // zero initial h16B slice: 64 batches x 8 units (16B per row)
    if (tid < 64)
        *(uint4*)(g_h16B + (size_t)(mb0 + tid)*H_ + uct*8) = make_uint4(0u,0u,0u,0u);

    float creg[2] = {0.f, 0.f};
    unsigned p = 1;
    hsync(half, p); p++;   // all half-grid h16 slices visible

    for (int t = 0; t < T_; t++) {
        lstm_phase<0>(t, mb0, uct, tid, g_h16B, g_h16A, sW, sA_base, creg, bb);
        hsync(half, p); p++;
        lstm_phase<1>(t, mb0, uct, tid, g_h16A, g_h16B, sW, sA_base, creg, bb);
        hsync(half, p); p++;
    }
}

// ---------------- output heads ----------------
__global__ void __launch_bounds__(512) output_kernel(const float* __restrict__ W_out,
                                                     const float* __restrict__ b_out,
                                                     const float* __restrict__ W_cls,
                                                     const float* __restrict__ b_cls,
                                                     float* __restrict__ out) {
    __shared__ float hb[H_];
    int b = blockIdx.x, tid = threadIdx.x;
    hb[tid] = g_h[b*H_ + tid];
    __syncthreads();

    int kk = tid >> 4, cc = tid & 15;
    float acc = 0.0f;
    #pragma unroll 8
    for (int k = 0; k < H_; k++)
        acc = fmaf(hb[k], W_cls[(size_t)kk*H_*CARD_ + k*CARD_ + cc], acc);
    out[12288 + b*512 + tid] = acc + b_cls[tid];

    if (tid < NCONT_) {
        float a2 = 0.0f;
        #pragma unroll 8
        for (int k = 0; k < H_; k++)
            a2 = fmaf(hb[k], W_out[k*NCONT_ + tid], a2);
        out[b*NCONT_ + tid] = a2 + b_out[tid];
    }
    out[77824  + b*512 + tid] = hb[tid];
    out[143360 + b*512 + tid] = g_c[b*H_ + tid];
}

// ---------------- entry ----------------
extern "C" void kernel_launch(void* const* d_in, const int* in_sizes, int n_in,
                              void* d_out, int out_size) {
    (void)in_sizes; (void)n_in; (void)out_size;
    const int*   unscaled = (const int*)  d_in[0];
    const float* scaled   = (const float*)d_in[1];
    const float* emb      = (const float*)d_in[2];
    const float* W_in     = (const float*)d_in[3];
    const float* b_in     = (const float*)d_in[4];
    const float* Wih0     = (const float*)d_in[5];
    const float* Whh0     = (const float*)d_in[6];
    const float* bih0     = (const float*)d_in[7];
    const float* bhh0     = (const float*)d_in[8];
    const float* Wih1     = (const float*)d_in[9];
    const float* Whh1     = (const float*)d_in[10];
    const float* bih1     = (const float*)d_in[11];
    const float* bhh1     = (const float*)d_in[12];
    const float* W_out    = (const float*)d_in[13];
    const float* b_out    = (const float*)d_in[14];
    const float* W_cls    = (const float*)d_in[15];
    const float* b_cls    = (const float*)d_in[16];
    float* out = (float*)d_out;

    cudaFuncSetAttribute(lstm_kernel,  cudaFuncAttributeMaxDynamicSharedMemorySize, LSTM_SMEM_B);
    cudaFuncSetAttribute(gemm1_kernel, cudaFuncAttributeMaxDynamicSharedMemorySize, 2*GT_BUF_B);
    cudaFuncSetAttribute(gemm2_kernel, cudaFuncAttributeMaxDynamicSharedMemorySize, 2*GT_BUF_B);

    prep_kernel<<<G4H_, H_>>>(Wih0, Whh0, Wih1, Whh1, bih0, bhh0, bih1, bhh1);
    prep_win_kernel<<<INPUT_LEN_, H_>>>(W_in);
    build_xin_kernel<<<BT_, INPUT_LEN_>>>(unscaled, scaled, emb);
    gemm1_kernel<<<dim3(BT_/128, H_/128), 256, 2*GT_BUF_B>>>(b_in);
    gemm2_kernel<<<dim3(BT_/128, G4H_/128), 256, 2*GT_BUF_B>>>();
    lstm_kernel<<<NBLK_, LSTM_THREADS, LSTM_SMEM_B>>>();
    output_kernel<<<B_, 512>>>(W_out, b_out, W_cls, b_cls, out);
}

// round 16
// speedup vs baseline: 1.2564x; 1.1030x over previous
#include <cuda_runtime.h>
#include <cuda_fp16.h>
#include <cstdint>

#define B_ 128
#define T_ 256
#define F_ 128
#define NCAT_ 32
#define CARD_ 16
#define E_ 8
#define H_ 512
#define INPUT_LEN_ 352
#define NCONT_ 96
#define BT_ (B_*T_)
#define G4H_ 2048
#define NBLK_ 128          // LSTM persistent grid
#define LSTM_THREADS 256
#define WSTRIDE 520        // padded k-stride (halves) for conflict-free weight LDS
#define IMG_HALVES (32*WSTRIDE)          // one image: 32 n-rows (8 units x 4 gates) x 520
#define CTA_IMG_HALVES (4*IMG_HALVES)    // L0hi,L0lo,L1hi,L1lo = 133120 B

typedef unsigned long long ull;

// ---------------- scratch (device globals) ----------------
__device__ __align__(128) __half g_xin16h[(size_t)BT_*INPUT_LEN_];
__device__ __align__(128) __half g_Win16h[(size_t)H_*INPUT_LEN_];
__device__ __align__(128) __half g_Win16l[(size_t)H_*INPUT_LEN_];
__device__ __align__(128) __half g_x16h[(size_t)BT_*H_];
__device__ __align__(128) float  g_X0 [(size_t)BT_*G4H_];
__device__ __align__(128) __half g_W16h[(size_t)G4H_*H_];
__device__ __align__(128) __half g_W16l[(size_t)G4H_*H_];
__device__ float  g_b0[G4H_];
__device__ float  g_b1[G4H_];
__device__ __align__(128) __half g_img[(size_t)64*CTA_IMG_HALVES];   // 64 unit-group images
__device__ __align__(128) __half g_h16A[B_*H_];   // h0 (layer0 output)
__device__ __align__(128) __half g_h16B[B_*H_];   // h  (layer1 output)
__device__ float  g_h [B_*H_];
__device__ float  g_c [B_*H_];
__device__ __align__(128) unsigned g_pcnt[64];    // [0]: batch-half 0, [32]: batch-half 1

// ---------------- helpers ----------------
__device__ __forceinline__ float sigf(float x) { return 1.0f / (1.0f + __expf(-x)); }
__device__ __forceinline__ float tanhfast(float x) { return 2.0f*sigf(2.0f*x) - 1.0f; }
__device__ __forceinline__ uint32_t smem_u32(const void* p) {
    uint32_t a;
    asm("{ .reg .u64 t; cvta.to.shared.u64 t, %1; cvt.u32.u64 %0, t; }" : "=r"(a) : "l"(p));
    return a;
}
__device__ __forceinline__ unsigned ldacq(const unsigned* p) {
    unsigned v;
    asm volatile("ld.global.acquire.gpu.u32 %0, [%1];" : "=r"(v) : "l"(p));
    return v;
}
__device__ __forceinline__ void mma_f32(float* d, const uint32_t* a, const uint32_t* b) {
    asm volatile("mma.sync.aligned.m16n8k16.row.col.f32.f16.f16.f32 "
        "{%0,%1,%2,%3}, {%4,%5,%6,%7}, {%8,%9}, {%0,%1,%2,%3};"
        : "+f"(d[0]), "+f"(d[1]), "+f"(d[2]), "+f"(d[3])
        : "r"(a[0]), "r"(a[1]), "r"(a[2]), "r"(a[3]), "r"(b[0]), "r"(b[1]));
}
__device__ __forceinline__ void mma_f16acc(uint32_t* d, const uint32_t* a, const uint32_t* b) {
    asm volatile("mma.sync.aligned.m16n8k16.row.col.f16.f16.f16.f16 "
        "{%0,%1}, {%2,%3,%4,%5}, {%6,%7}, {%0,%1};"
        : "+r"(d[0]), "+r"(d[1])
        : "r"(a[0]), "r"(a[1]), "r"(a[2]), "r"(a[3]), "r"(b[0]), "r"(b[1]));
}
#define CP_ASYNC16(dst_u32, src_ptr) \
    asm volatile("cp.async.cg.shared.global [%0], [%1], 16;" :: "r"(dst_u32), "l"(src_ptr) : "memory")
#define CP_COMMIT() asm volatile("cp.async.commit_group;" ::: "memory")
#define CP_WAIT(n)  asm volatile("cp.async.wait_group %0;" :: "n"(n) : "memory")
#define LDSM_X4(r0,r1,r2,r3, a) \
    asm volatile("ldmatrix.sync.aligned.m8n8.x4.shared.b16 {%0,%1,%2,%3}, [%4];" \
        : "=r"(r0), "=r"(r1), "=r"(r2), "=r"(r3) : "r"(a))
#define NAMED_BAR(id) asm volatile("bar.sync %0, 64;" :: "r"(id) : "memory")

// half-grid barrier, split: arrive (after CTA-wide store visibility) / wait (per-warp poll)
__device__ __forceinline__ void harrive(int half) {
    __syncthreads();
    if (threadIdx.x == 0) {
        __threadfence();
        atomicAdd(&g_pcnt[half*32], 1u);
    }
}
__device__ __forceinline__ void hwait(int half, unsigned p) {
    const unsigned target = 64u * p;
    if ((threadIdx.x & 31) == 0) {
        if (ldacq(&g_pcnt[half*32]) < target) {
            do { __nanosleep(20); } while (ldacq(&g_pcnt[half*32]) < target);
        }
    }
    __syncwarp();
}

// ---------------- prep ----------------
// unit-group images: uct = u>>3 owns units [uct*8,+8). Row layout within 32-row image:
// nh = (u>>2)&1 selects 16-row half; q = u&3, gate g:
// n_local = nh*16 + (g<2 ? 2q+g : 2q+8+(g-2))
__global__ void prep_kernel(const float* __restrict__ Wih0, const float* __restrict__ Whh0,
                            const float* __restrict__ Wih1, const float* __restrict__ Whh1,
                            const float* __restrict__ bih0, const float* __restrict__ bhh0,
                            const float* __restrict__ bih1, const float* __restrict__ bhh1) {
    int n = blockIdx.x;      // 0..2047
    int k = threadIdx.x;     // 0..511
    if (blockIdx.x == 0 && threadIdx.x < 64) g_pcnt[threadIdx.x] = 0u;

    float wih0 = Wih0[n*H_ + k];
    float whh0 = Whh0[n*H_ + k];
    float w1   = Wih1[n*H_ + k] + Whh1[n*H_ + k];

    __half wh = __float2half_rn(wih0);
    g_W16h[(size_t)n*H_ + k] = wh;
    g_W16l[(size_t)n*H_ + k] = __float2half_rn((wih0 - __half2float(wh))*2048.0f);

    int g = n >> 9, u = n & 511;
    int uct = u >> 3;
    int nh = (u >> 2) & 1;
    int q = u & 3;
    int n_local = nh*16 + ((g < 2) ? (2*q + g) : (2*q + 8 + (g - 2)));
    size_t base = (size_t)uct * CTA_IMG_HALVES + (size_t)n_local * WSTRIDE + k;
    __half h0hi = __float2half(whh0);
    __half h0lo = __float2half((whh0 - __half2float(h0hi)) * 2048.0f);
    __half h1hi = __float2half(w1);
    __half h1lo = __float2half((w1 - __half2float(h1hi)) * 2048.0f);
    g_img[base + 0*IMG_HALVES] = h0hi;
    g_img[base + 1*IMG_HALVES] = h0lo;
    g_img[base + 2*IMG_HALVES] = h1hi;
    g_img[base + 3*IMG_HALVES] = h1lo;

    if (k == 0) {
        g_b0[n] = bih0[n] + bhh0[n];
        g_b1[n] = bih1[n] + bhh1[n];
    }
}

__global__ void prep_win_kernel(const float* __restrict__ W_in) {
    int k = blockIdx.x;      // 0..351
    int n = threadIdx.x;     // 0..511
    float v = W_in[(size_t)k*H_ + n];
    __half hi = __float2half_rn(v);
    g_Win16h[(size_t)n*INPUT_LEN_ + k] = hi;
    g_Win16l[(size_t)n*INPUT_LEN_ + k] = __float2half_rn((v - __half2float(hi))*2048.0f);
}

// ---------------- build xin (fp16 hi only) ----------------
__global__ void build_xin_kernel(const int* __restrict__ unscaled,
                                 const float* __restrict__ scaled,
                                 const float* __restrict__ emb) {
    int bt = blockIdx.x;
    int i  = threadIdx.x;
    int k  = i / 11;
    int j  = i - k*11;
    float v;
    if (j < 8) {
        int cid = unscaled[(size_t)bt*F_ + 4*k];
        v = emb[(k*CARD_ + cid)*E_ + j];
    } else {
        v = scaled[(size_t)bt*F_ + 4*k + (j - 8) + 1];
    }
    g_xin16h[(size_t)bt*INPUT_LEN_ + i] = __float2half_rn(v);
}

// ---------------- HMMA GEMM tiles ----------------
#define GT_BUF_B 30720
#define GT_A_OFF 0
#define GT_WH_OFF 10240
#define GT_WL_OFF 20480

__device__ __forceinline__ void gt_stage(uint32_t sbase, int buf, int m0, int n0, int kb, int tid,
                                         const __half* __restrict__ A, int strideA,
                                         const __half* __restrict__ Wh,
                                         const __half* __restrict__ Wl, int strideW) {
    uint32_t b = sbase + buf*GT_BUF_B;
    #pragma unroll
    for (int rep = 0; rep < 2; rep++) {
        int i = rep*256 + tid;
        int row = i >> 2, c = i & 3;
        uint32_t doff = (uint32_t)(row*40 + c*8)*2;
        CP_ASYNC16(b + GT_A_OFF  + doff, A  + (size_t)(m0+row)*strideA + kb + c*8);
        CP_ASYNC16(b + GT_WH_OFF + doff, Wh + (size_t)(n0+row)*strideW + kb + c*8);
        CP_ASYNC16(b + GT_WL_OFF + doff, Wl + (size_t)(n0+row)*strideW + kb + c*8);
    }
}

template<int KITERS>
__device__ __forceinline__ void gt_mainloop(uint32_t sbase, const __half* g2s,
                                            int m0, int n0, int tid,
                                            const __half* __restrict__ A, int strideA,
                                            const __half* __restrict__ Wh,
                                            const __half* __restrict__ Wl, int strideW,
                                            float accM[2][8][4], uint32_t accC[2][8][2]) {
    const int lane = tid & 31, wid = tid >> 5;
    const int wm = wid & 3, wn = wid >> 2;
    const int r = lane >> 2, q = lane & 3;

    gt_stage(sbase, 0, m0, n0, 0, tid, A, strideA, Wh, Wl, strideW); CP_COMMIT();

    #pragma unroll 1
    for (int it = 0; it < KITERS; it++) {
        if (it < KITERS-1) {
            gt_stage(sbase, (it+1)&1, m0, n0, (it+1)*32, tid, A, strideA, Wh, Wl, strideW);
            CP_COMMIT();
            CP_WAIT(1);
        } else {
            CP_WAIT(0);
        }
        __syncthreads();
        const __half* sA  = g2s + ((it&1)*GT_BUF_B + GT_A_OFF )/2;
        const __half* sWh = g2s + ((it&1)*GT_BUF_B + GT_WH_OFF)/2;
        const __half* sWl = g2s + ((it&1)*GT_BUF_B + GT_WL_OFF)/2;
        #pragma unroll
        for (int kk = 0; kk < 32; kk += 16) {
            uint32_t a[2][4];
            #pragma unroll
            for (int mt = 0; mt < 2; mt++) {
                const __half* p = sA + (wm*32 + mt*16 + r)*40 + kk + q*2;
                a[mt][0] = *(const uint32_t*)p;
                a[mt][1] = *(const uint32_t*)(p + 8*40);
                a[mt][2] = *(const uint32_t*)(p + 8);
                a[mt][3] = *(const uint32_t*)(p + 8*40 + 8);
            }
            #pragma unroll
            for (int nt = 0; nt < 8; nt++) {
                const __half* ph = sWh + (wn*64 + nt*8 + r)*40 + kk + q*2;
                const __half* pl = sWl + (wn*64 + nt*8 + r)*40 + kk + q*2;
                uint32_t bh[2] = {*(const uint32_t*)ph, *(const uint32_t*)(ph+8)};
                uint32_t bl[2] = {*(const uint32_t*)pl, *(const uint32_t*)(pl+8)};
                #pragma unroll
                for (int mt = 0; mt < 2; mt++) {
                    mma_f32(accM[mt][nt], a[mt], bh);
                    mma_f16acc(accC[mt][nt], a[mt], bl);
                }
            }
        }
        __syncthreads();
    }
}

// gemm1: x = relu(xin@W_in + b_in), fp16 output
__global__ void __launch_bounds__(256, 2) gemm1_kernel(const float* __restrict__ b_in) {
    extern __shared__ __half g2s[];
    const int tid = threadIdx.x, lane = tid & 31, wid = tid >> 5;
    const int wm = wid & 3, wn = wid >> 2;
    const int r = lane >> 2, q = lane & 3;
    const int m0 = blockIdx.x * 128;
    const int n0 = blockIdx.y * 128;
    uint32_t sbase = smem_u32(g2s);

    float accM[2][8][4]; uint32_t accC[2][8][2];
    #pragma unroll
    for (int mt = 0; mt < 2; mt++)
        #pragma unroll
        for (int nt = 0; nt < 8; nt++) {
            #pragma unroll
            for (int i = 0; i < 4; i++) accM[mt][nt][i] = 0.0f;
            accC[mt][nt][0] = 0u; accC[mt][nt][1] = 0u;
        }

    gt_mainloop<11>(sbase, g2s, m0, n0, tid, g_xin16h, INPUT_LEN_, g_Win16h, g_Win16l, INPUT_LEN_, accM, accC);

    const float s = 1.0f/2048.0f;
    #pragma unroll
    for (int mt = 0; mt < 2; mt++) {
        int gr0 = m0 + wm*32 + mt*16 + r;
        #pragma unroll
        for (int nt = 0; nt < 8; nt++) {
            int col = n0 + wn*64 + nt*8 + q*2;
            float bv0 = b_in[col], bv1 = b_in[col+1];
            __half2 lo01 = *reinterpret_cast<__half2*>(&accC[mt][nt][0]);
            __half2 lo23 = *reinterpret_cast<__half2*>(&accC[mt][nt][1]);
            float v00 = fmaxf(accM[mt][nt][0] + __half2float(__low2half(lo01))*s + bv0, 0.f);
            float v01 = fmaxf(accM[mt][nt][1] + __half2float(__high2half(lo01))*s + bv1, 0.f);
            float v10 = fmaxf(accM[mt][nt][2] + __half2float(__low2half(lo23))*s + bv0, 0.f);
            float v11 = fmaxf(accM[mt][nt][3] + __half2float(__high2half(lo23))*s + bv1, 0.f);
            size_t o0 = (size_t)gr0*H_ + col, o1 = (size_t)(gr0+8)*H_ + col;
            *(__half2*)(g_x16h + o0) = __halves2half2(__float2half_rn(v00), __float2half_rn(v01));
            *(__half2*)(g_x16h + o1) = __halves2half2(__float2half_rn(v10), __float2half_rn(v11));
        }
    }
}

// gemm2: X0 = x@Wih0^T + b0 (fp32 out, [bt][gate*H+unit])
__global__ void __launch_bounds__(256, 2) gemm2_kernel() {
    extern __shared__ __half g2s[];
    const int tid = threadIdx.x, lane = tid & 31, wid = tid >> 5;
    const int wm = wid & 3, wn = wid >> 2;
    const int r = lane >> 2, q = lane & 3;
    const int m0 = blockIdx.x * 128;
    const int n0 = blockIdx.y * 128;
    uint32_t sbase = smem_u32(g2s);

    float accM[2][8][4]; uint32_t accC[2][8][2];
    #pragma unroll
    for (int mt = 0; mt < 2; mt++)
        #pragma unroll
        for (int nt = 0; nt < 8; nt++) {
            #pragma unroll
            for (int i = 0; i < 4; i++) accM[mt][nt][i] = 0.0f;
            accC[mt][nt][0] = 0u; accC[mt][nt][1] = 0u;
        }

    gt_mainloop<16>(sbase, g2s, m0, n0, tid, g_x16h, H_, g_W16h, g_W16l, H_, accM, accC);

    const float s = 1.0f/2048.0f;
    #pragma unroll
    for (int mt = 0; mt < 2; mt++) {
        int gr0 = m0 + wm*32 + mt*16 + r;
        #pragma unroll
        for (int nt = 0; nt < 8; nt++) {
            int col = n0 + wn*64 + nt*8 + q*2;
            float b0a = g_b0[col], b0b = g_b0[col+1];
            __half2 lo01 = *reinterpret_cast<__half2*>(&accC[mt][nt][0]);
            __half2 lo23 = *reinterpret_cast<__half2*>(&accC[mt][nt][1]);
            float2 o0, o1;
            o0.x = accM[mt][nt][0] + __half2float(__low2half(lo01))*s + b0a;
            o0.y = accM[mt][nt][1] + __half2float(__high2half(lo01))*s + b0b;
            o1.x = accM[mt][nt][2] + __half2float(__low2half(lo23))*s + b0a;
            o1.y = accM[mt][nt][3] + __half2float(__high2half(lo23))*s + b0b;
            *(float2*)(g_X0 + (size_t)gr0*G4H_ + col) = o0;
            *(float2*)(g_X0 + (size_t)(gr0+8)*G4H_ + col) = o1;
        }
    }
}

// ---------------- HMMA persistent LSTM — R13 structure + arrive/wait split, X0 prefetch in wait window
// CTA ct: batches [(ct&1)*64, +64), units [(ct>>1)*8, +8) (32 gate-rows).
// Warp w = bm*2 + nh: batches [bm*16,+16) of CTA range, unit-half nh (4 units, 16 rows).
#define SH_OFF CTA_IMG_HALVES
#define LSTM_SMEM_B ((CTA_IMG_HALVES + 64*H_)*2)   // 133120 + 65536 = 198656

template<int LAYER>
__device__ __forceinline__ void lstm_phase(int t, int mb0, int uct, int tid,
                                           const __half* __restrict__ hsrc,
                                           __half* __restrict__ hdst,
                                           const __half* __restrict__ sW,
                                           uint32_t sA_base,
                                           float* __restrict__ creg,
                                           const float* __restrict__ bb,
                                           const float* __restrict__ x0r) {   // [8] prefetched (layer 0)
    const int w = tid >> 5, lane = tid & 31;
    const int bm = w >> 1, nh = w & 1;
    const int q = lane & 3, r = lane >> 2;
    const int unit = uct*8 + nh*4 + q;
    const int gb0 = mb0 + bm*16;
    const uint32_t pairbase = sA_base + (uint32_t)bm*16384;

    // stage this warp's 8 rows of the pair's 16-row buffer, 4 chunks of 128 cols
    #pragma unroll
    for (int j = 0; j < 4; j++) {
        #pragma unroll
        for (int seg = 0; seg < 4; seg++) {
            int i = seg*32 + lane;
            int rl = i >> 4, c = i & 15;
            int row = nh*8 + rl;
            uint32_t dst = pairbase + (uint32_t)row*1024 + ((uint32_t)((j*16 + c) ^ (row & 7)) << 4);
            CP_ASYNC16(dst, hsrc + (size_t)(gb0 + row)*H_ + (j*16 + c)*8);
        }
        CP_COMMIT();
    }

    float accH[2][4];
    uint32_t accLC[2][2];
    #pragma unroll
    for (int nt = 0; nt < 2; nt++) {
        #pragma unroll
        for (int i = 0; i < 4; i++) accH[nt][i] = 0.f;
        accLC[nt][0] = 0u; accLC[nt][1] = 0u;
    }

    const uint32_t rowAddr = pairbase + (uint32_t)(lane & 15)*1024;
    const int sw = lane & 7;
    const int khalf = lane >> 4;
    const __half* wHi = sW + (LAYER*2 + 0)*IMG_HALVES + (nh*16 + r)*WSTRIDE + q*2;
    const __half* wLo = wHi + IMG_HALVES;

    auto mma_chunk = [&](int j) {
        #pragma unroll
        for (int kk = 0; kk < 8; kk++) {
            int k0 = j*128 + kk*16;
            uint32_t coff = ((uint32_t)((j*16 + kk*2 + khalf) ^ sw)) << 4;
            uint32_t a[4];
            LDSM_X4(a[0], a[1], a[2], a[3], rowAddr + coff);
            #pragma unroll
            for (int nt = 0; nt < 2; nt++) {
                const __half* ph = wHi + nt*8*WSTRIDE + k0;
                const __half* pl = wLo + nt*8*WSTRIDE + k0;
                uint32_t bh[2] = {*(const uint32_t*)ph, *(const uint32_t*)(ph+8)};
                uint32_t bl[2] = {*(const uint32_t*)pl, *(const uint32_t*)(pl+8)};
                mma_f32(accH[nt], a, bh);
                mma_f16acc(accLC[nt], a, bl);
            }
        }
    };

    CP_WAIT(3); NAMED_BAR(1 + bm); mma_chunk(0);
    CP_WAIT(2); NAMED_BAR(1 + bm); mma_chunk(1);
    CP_WAIT(1); NAMED_BAR(1 + bm); mma_chunk(2);
    CP_WAIT(0); NAMED_BAR(1 + bm); mma_chunk(3);

    const float s = 1.0f / 2048.0f;
    #pragma unroll
    for (int hr = 0; hr < 2; hr++) {
        int batch = gb0 + hr*8 + r;
        __half2 l0 = *reinterpret_cast<__half2*>(&accLC[0][hr]);   // gates i,f
        __half2 l1 = *reinterpret_cast<__half2*>(&accLC[1][hr]);   // gates g,o
        float vi = accH[0][hr*2+0] + __half2float(__low2half(l0))*s;
        float vf = accH[0][hr*2+1] + __half2float(__high2half(l0))*s;
        float vg = accH[1][hr*2+0] + __half2float(__low2half(l1))*s;
        float vo = accH[1][hr*2+1] + __half2float(__high2half(l1))*s;
        if (LAYER == 0) {
            vi += x0r[hr*4+0]; vf += x0r[hr*4+1]; vg += x0r[hr*4+2]; vo += x0r[hr*4+3];
        } else {
            vi += bb[0]; vf += bb[1]; vg += bb[2]; vo += bb[3];
        }
        float c = creg[hr];
        float cn = sigf(vf)*c + sigf(vi)*tanhfast(vg);
        creg[hr] = cn;
        float hv = sigf(vo)*tanhfast(cn);
        hdst[(size_t)batch*H_ + unit] = __float2half_rn(hv);
        if (LAYER == 1 && t == T_-1) {
            g_h[batch*H_ + unit] = hv;
            g_c[batch*H_ + unit] = cn;
        }
    }
}

__global__ void __launch_bounds__(LSTM_THREADS, 1) lstm_kernel() {
    extern __shared__ __half smemL[];
    __half* sW = smemL;
    uint32_t sA_base = smem_u32(smemL + SH_OFF);
    const int tid = threadIdx.x, lane = tid & 31;
    const int w = tid >> 5;
    const int ct = blockIdx.x;
    const int half = ct & 1;
    const int mb0 = half * 64;
    const int uct = ct >> 1;
    const int bm = w >> 1, nh = w & 1;
    const int q = lane & 3, r = lane >> 2;
    const int gb0 = mb0 + bm*16;
    const int unit = uct*8 + nh*4 + q;

    // copy resident weight images (133120 B; sibling CTAs share the same image -> L2 hits)
    {
        const uint4* src = (const uint4*)(g_img + (size_t)uct*CTA_IMG_HALVES);
        uint4* dst = (uint4*)sW;
        #pragma unroll 4
        for (int i = tid; i < CTA_IMG_HALVES/8; i += LSTM_THREADS)
            dst[i] = src[i];
    }
    float bb[4];
    #pragma unroll
    for (int g = 0; g < 4; g++) bb[g] = g_b1[g*H_ + unit];

    // zero initial h16B slice: 64 batches x 8 units (16B per row)
    if (tid < 64)
        *(uint4*)(g_h16B + (size_t)(mb0 + tid)*H_ + uct*8) = make_uint4(0u,0u,0u,0u);

    float creg[2] = {0.f, 0.f};
    float x0buf[8];

    auto prefetch_x0 = [&](int t) {
        #pragma unroll
        for (int hr = 0; hr < 2; hr++) {
            int batch = gb0 + hr*8 + r;
            const float* xb = g_X0 + ((size_t)batch*T_ + t)*G4H_ + unit;
            #pragma unroll
            for (int g = 0; g < 4; g++) x0buf[hr*4+g] = __ldg(xb + g*H_);
        }
    };

    unsigned p = 1;
    harrive(half);          // init production (zeros)
    prefetch_x0(0);         // overlap initial wait
    hwait(half, p); p++;

    for (int t = 0; t < T_; t++) {
        lstm_phase<0>(t, mb0, uct, tid, g_h16B, g_h16A, sW, sA_base, creg, bb, x0buf);
        harrive(half);
        hwait(half, p); p++;
        lstm_phase<1>(t, mb0, uct, tid, g_h16A, g_h16B, sW, sA_base, creg, bb, x0buf);
        if (t < T_-1) {
            harrive(half);
            prefetch_x0(t + 1);    // overlaps the barrier wait
            hwait(half, p); p++;
        }
    }
}

// ---------------- output heads ----------------
__global__ void __launch_bounds__(512) output_kernel(const float* __restrict__ W_out,
                                                     const float* __restrict__ b_out,
                                                     const float* __restrict__ W_cls,
                                                     const float* __restrict__ b_cls,
                                                     float* __restrict__ out) {
    __shared__ float hb[H_];
    int b = blockIdx.x, tid = threadIdx.x;
    hb[tid] = g_h[b*H_ + tid];
    __syncthreads();

    int kk = tid >> 4, cc = tid & 15;
    float acc = 0.0f;
    #pragma unroll 8
    for (int k = 0; k < H_; k++)
        acc = fmaf(hb[k], W_cls[(size_t)kk*H_*CARD_ + k*CARD_ + cc], acc);
    out[12288 + b*512 + tid] = acc + b_cls[tid];

    if (tid < NCONT_) {
        float a2 = 0.0f;
        #pragma unroll 8
        for (int k = 0; k < H_; k++)
            a2 = fmaf(hb[k], W_out[k*NCONT_ + tid], a2);
        out[b*NCONT_ + tid] = a2 + b_out[tid];
    }
    out[77824  + b*512 + tid] = hb[tid];
    out[143360 + b*512 + tid] = g_c[b*H_ + tid];
}

// ---------------- entry ----------------
extern "C" void kernel_launch(void* const* d_in, const int* in_sizes, int n_in,
                              void* d_out, int out_size) {
    (void)in_sizes; (void)n_in; (void)out_size;
    const int*   unscaled = (const int*)  d_in[0];
    const float* scaled   = (const float*)d_in[1];
    const float* emb      = (const float*)d_in[2];
    const float* W_in     = (const float*)d_in[3];
    const float* b_in     = (const float*)d_in[4];
    const float* Wih0     = (const float*)d_in[5];
    const float* Whh0     = (const float*)d_in[6];
    const float* bih0     = (const float*)d_in[7];
    const float* bhh0     = (const float*)d_in[8];
    const float* Wih1     = (const float*)d_in[9];
    const float* Whh1     = (const float*)d_in[10];
    const float* bih1     = (const float*)d_in[11];
    const float* bhh1     = (const float*)d_in[12];
    const float* W_out    = (const float*)d_in[13];
    const float* b_out    = (const float*)d_in[14];
    const float* W_cls    = (const float*)d_in[15];
    const float* b_cls    = (const float*)d_in[16];
    float* out = (float*)d_out;

    cudaFuncSetAttribute(lstm_kernel,  cudaFuncAttributeMaxDynamicSharedMemorySize, LSTM_SMEM_B);
    cudaFuncSetAttribute(gemm1_kernel, cudaFuncAttributeMaxDynamicSharedMemorySize, 2*GT_BUF_B);
    cudaFuncSetAttribute(gemm2_kernel, cudaFuncAttributeMaxDynamicSharedMemorySize, 2*GT_BUF_B);

    prep_kernel<<<G4H_, H_>>>(Wih0, Whh0, Wih1, Whh1, bih0, bhh0, bih1, bhh1);
    prep_win_kernel<<<INPUT_LEN_, H_>>>(W_in);
    build_xin_kernel<<<BT_, INPUT_LEN_>>>(unscaled, scaled, emb);
    gemm1_kernel<<<dim3(BT_/128, H_/128), 256, 2*GT_BUF_B>>>(b_in);
    gemm2_kernel<<<dim3(BT_/128, G4H_/128), 256, 2*GT_BUF_B>>>();
    lstm_kernel<<<NBLK_, LSTM_THREADS, LSTM_SMEM_B>>>();
    output_kernel<<<B_, 512>>>(W_out, b_out, W_cls, b_cls, out);
}